// round 7
// baseline (speedup 1.0000x reference)
#include <cuda_runtime.h>
#include <cstdint>

// CML scores: out[u,i] = 2*dot(U[ids[u]], I[i]) - ||u||^2 - ||i||^2
// GEMM M=256 x N=500000 x K=64, mma.sync.m16n8k8 tf32 (fp32 accum).
// One 1024-thread CTA per SM (32 warps), tile 256x128.
// A: converted once (cvt.rna tf32) into frag-layout SMEM with k-permutation.
// B: cp.async 4-stage raw fp32 (no conversion; HMMA truncates to tf32),
//    pitch 72 floats -> conflict-free LDS.64 fragment reads.
// Epilogue: column permutation -> pure STG.128 full-sector stores.

#define THREADS   1024
#define BN        128
#define STAGES    4
#define BPITCH    288                       // 72 floats per B row
#define BSTAGE_SZ (BN * BPITCH)             // 36864
#define SM_AFRAG  0                         // 8ks x 16mt x 512B = 64KB
#define SM_BSTAGE 65536
#define SM_USQ    (SM_BSTAGE + STAGES * BSTAGE_SZ)   // 212992
#define SM_ISQ    (SM_USQ + 1024)                    // 214016
#define SM_TOTAL  (SM_ISQ + 512)                     // 214528

__device__ __forceinline__ uint32_t smem_u32(const void* p) {
    uint32_t a;
    asm("{ .reg .u64 t; cvta.to.shared.u64 t, %1; cvt.u32.u64 %0, t; }"
        : "=r"(a) : "l"(p));
    return a;
}
__device__ __forceinline__ uint32_t cvt_tf32(float x) {
    uint32_t r;
    asm("cvt.rna.tf32.f32 %0, %1;" : "=r"(r) : "f"(x));
    return r;
}
__device__ __forceinline__ void mma_tf32(float* c, const uint32_t* a,
                                         uint32_t b0, uint32_t b1) {
    asm volatile(
        "mma.sync.aligned.m16n8k8.row.col.f32.tf32.tf32.f32 "
        "{%0,%1,%2,%3}, {%4,%5,%6,%7}, {%8,%9}, {%0,%1,%2,%3};"
        : "+f"(c[0]), "+f"(c[1]), "+f"(c[2]), "+f"(c[3])
        : "r"(a[0]), "r"(a[1]), "r"(a[2]), "r"(a[3]), "r"(b0), "r"(b1));
}
__device__ __forceinline__ void cp_async16(uint32_t dst, const void* src, int sz) {
    asm volatile("cp.async.ca.shared.global [%0], [%1], 16, %2;"
                 :: "r"(dst), "l"(src), "r"(sz) : "memory");
}
__device__ __forceinline__ void cp_commit() {
    asm volatile("cp.async.commit_group;" ::: "memory");
}
__device__ __forceinline__ void cp_wait2() {
    asm volatile("cp.async.wait_group 2;" ::: "memory");
}

// SMEM B row chi <-> output item offset (column permutation for STG.128):
// chi = 16P + 8e + 2j + d   ->   item_off = 16P + 4j + 2e + d
__device__ __forceinline__ int perm_item(int chi) {
    return (chi & ~15) + (((chi >> 1) & 3) << 2) + (((chi >> 3) & 1) << 1)
         + (chi & 1);
}

// Issue cp.asyncs for one B tile into a stage (2 x 16B chunks per thread).
__device__ __forceinline__ void issueB(const float* __restrict__ I, int tile,
                                       int nItems, uint32_t stageBase, int tid) {
    #pragma unroll
    for (int h = 0; h < 2; h++) {
        const int chunk = tid + h * THREADS;
        const int chi = chunk >> 4, c = chunk & 15;
        const long item = (long)tile * BN + perm_item(chi);
        const int  valid = item < nItems;
        const float* src = I + (valid ? item * 64 + c * 4 : 0);
        cp_async16(stageBase + chi * BPITCH + c * 16, src, valid ? 16 : 0);
    }
}

__global__ __launch_bounds__(THREADS, 1)
void cml_mma(const int* __restrict__ ids,
             const float* __restrict__ U,
             const float* __restrict__ I,
             float* __restrict__ out,
             int nItems)
{
    extern __shared__ char smem[];
    const uint32_t sb = smem_u32(smem);
    float* usq = (float*)(smem + SM_USQ);
    float* isq = (float*)(smem + SM_ISQ);

    const int tid  = threadIdx.x;
    const int lane = tid & 31;
    const int wid  = tid >> 5;
    const int wm   = wid >> 2;      // 0..7: 32 user rows (2 mtiles)
    const int wn   = wid & 3;       // 0..3: 32 item cols (4 ntiles)

    // ---- Prologue: A (256 users) -> k-permuted tf32 frag layout + usq -----
    {
        const int u = tid >> 2, qq = tid & 3;        // 16 k-values per thread
        const int uid = ids[u];
        const float* up = U + (size_t)uid * 64 + qq * 16;
        float a[16];
        #pragma unroll
        for (int w = 0; w < 4; w++) {
            const float4 t = ((const float4*)up)[w];
            a[4*w] = t.x; a[4*w+1] = t.y; a[4*w+2] = t.z; a[4*w+3] = t.w;
        }
        float s = 0.f;
        #pragma unroll
        for (int j = 0; j < 16; j++) s = fmaf(a[j], a[j], s);
        s += __shfl_xor_sync(0xffffffffu, s, 1);
        s += __shfl_xor_sync(0xffffffffu, s, 2);
        if (qq == 0) usq[u] = s;

        const int mt = u >> 4, rr = u & 7, r8 = (u >> 3) & 1;
        #pragma unroll
        for (int j = 0; j < 16; j++) {
            const int k = qq * 16 + j;
            const int ks = k >> 3, w = k & 7, m = w >> 1, half = w & 1;
            // frag group l = rr*4+m, slot = r8 + 2*half (k-perm: raw 2m,2m+1
            // occupy mma k-slots m, m+4)
            *(uint32_t*)(smem + (ks * 16 + mt) * 512 + (rr * 4 + m) * 16
                         + (r8 + 2 * half) * 4) = cvt_tf32(a[j]);
        }
    }

    // ---- cp.async pipeline prologue: fill stages 0..2 ---------------------
    const int NT = (nItems + BN - 1) >> 7;
    #pragma unroll
    for (int s = 0; s < STAGES - 1; s++) {
        const int t = blockIdx.x + s * gridDim.x;
        if (t < NT) issueB(I, t, nItems, sb + SM_BSTAGE + s * BSTAGE_SZ, tid);
        cp_commit();
    }

    int it = 0;
    for (int tile = blockIdx.x; tile < NT; tile += gridDim.x, it++) {
        const int stage = it & (STAGES - 1);
        const char* bp = smem + SM_BSTAGE + stage * BSTAGE_SZ;

        cp_wait2();
        __syncthreads();                 // stage data ready; prev stage free

        // ---- item norms (exact fp32) from staged raw B --------------------
        {
            const int chi = tid >> 3, q = tid & 7;
            const char* p = bp + chi * BPITCH + q * 32;
            const float4 v0 = *(const float4*)p;
            const float4 v1 = *(const float4*)(p + 16);
            float s = v0.x*v0.x + v0.y*v0.y + v0.z*v0.z + v0.w*v0.w
                    + v1.x*v1.x + v1.y*v1.y + v1.z*v1.z + v1.w*v1.w;
            s += __shfl_xor_sync(0xffffffffu, s, 1);
            s += __shfl_xor_sync(0xffffffffu, s, 2);
            s += __shfl_xor_sync(0xffffffffu, s, 4);
            if (q == 0) isq[chi] = s;    // indexed by SMEM row chi
        }

        // ---- issue loads 3 tiles ahead (into just-freed stage) ------------
        {
            const int t = tile + (STAGES - 1) * gridDim.x;
            if (t < NT)
                issueB(I, t, nItems,
                       sb + SM_BSTAGE + ((it + STAGES - 1) & (STAGES - 1)) * BSTAGE_SZ,
                       tid);
            cp_commit();
        }
        __syncthreads();                 // isq visible to all warps

        // ---- MMA: 2 mtiles x 4 ntiles x 8 ksteps --------------------------
        float acc[2][4][4];
        #pragma unroll
        for (int a = 0; a < 2; a++)
            #pragma unroll
            for (int b = 0; b < 4; b++)
                #pragma unroll
                for (int c = 0; c < 4; c++) acc[a][b][c] = 0.f;

        #pragma unroll
        for (int ks = 0; ks < 8; ks++) {
            const uint4 a0 = *(const uint4*)(smem + (ks * 16 + wm * 2    ) * 512
                                             + lane * 16);
            const uint4 a1 = *(const uint4*)(smem + (ks * 16 + wm * 2 + 1) * 512
                                             + lane * 16);
            #pragma unroll
            for (int n = 0; n < 4; n++) {
                // raw fp32 pair (k = ks*8+2m, +1) = mma k-slots (m, m+4)
                const uint2 b = *(const uint2*)(bp
                    + ((wn * 4 + n) * 8 + (lane >> 2)) * BPITCH
                    + ks * 32 + (lane & 3) * 8);
                mma_tf32(acc[0][n], (const uint32_t*)&a0, b.x, b.y);
                mma_tf32(acc[1][n], (const uint32_t*)&a1, b.x, b.y);
            }
        }

        // ---- Epilogue: score = 2c - usq - isq, STG.128 --------------------
        #pragma unroll
        for (int mt = 0; mt < 2; mt++) {
            const int rg = wm * 32 + mt * 16 + (lane >> 2);
            const float u0 = usq[rg], u1 = usq[rg + 8];
            const size_t r0 = (size_t)rg * (size_t)nItems;
            const size_t r1 = r0 + (size_t)8 * (size_t)nItems;
            #pragma unroll
            for (int qh = 0; qh < 2; qh++) {
                const int P = wn * 2 + qh;
                const int col = tile * BN + P * 16 + (lane & 3) * 4;
                if (col < nItems) {
                    const float2 iqa = *(const float2*)&isq[P * 16 + (lane & 3) * 2];
                    const float2 iqb = *(const float2*)&isq[P * 16 + 8 + (lane & 3) * 2];
                    const float* e0 = acc[mt][2 * qh];
                    const float* e1 = acc[mt][2 * qh + 1];
                    float4 v0, v1;
                    v0.x = fmaf(2.f, e0[0], -(u0 + iqa.x));
                    v0.y = fmaf(2.f, e0[1], -(u0 + iqa.y));
                    v0.z = fmaf(2.f, e1[0], -(u0 + iqb.x));
                    v0.w = fmaf(2.f, e1[1], -(u0 + iqb.y));
                    v1.x = fmaf(2.f, e0[2], -(u1 + iqa.x));
                    v1.y = fmaf(2.f, e0[3], -(u1 + iqa.y));
                    v1.z = fmaf(2.f, e1[2], -(u1 + iqb.x));
                    v1.w = fmaf(2.f, e1[3], -(u1 + iqb.y));
                    *(float4*)(out + r0 + col) = v0;
                    *(float4*)(out + r1 + col) = v1;
                }
            }
        }
    }
}

extern "C" void kernel_launch(void* const* d_in, const int* in_sizes, int n_in,
                              void* d_out, int out_size) {
    const int*   ids = (const int*)d_in[0];     // [256]
    const float* U   = (const float*)d_in[1];   // [100000, 64]
    const float* I   = (const float*)d_in[2];   // [500000, 64]
    float*       out = (float*)d_out;           // [256, 500000]

    const int nItems = in_sizes[2] / 64;

    int nsm = 148;
    cudaDeviceGetAttribute(&nsm, cudaDevAttrMultiProcessorCount, 0);

    cudaFuncSetAttribute(cml_mma, cudaFuncAttributeMaxDynamicSharedMemorySize,
                         SM_TOTAL);
    cml_mma<<<nsm, THREADS, SM_TOTAL>>>(ids, U, I, out, nItems);
}

// round 12
// speedup vs baseline: 1.1766x; 1.1766x over previous
#include <cuda_runtime.h>
#include <cstdint>

// CML scores: out[u,i] = 2*dot(U[ids[u]], I[i]) - ||u||^2 - ||i||^2
// GEMM M=256 x N=500000 x K=64, mma.sync.m16n8k8 tf32 (fp32 accum).
// 2 CTAs/SM x 256 threads (independent barrier domains), tile 256x64.
// A: converted once (cvt.rna tf32) into frag-layout SMEM (k-permuted).
// B: cp.async.cg raw fp32, 2 stages (HMMA truncates fp32->tf32 in-datapath);
//    pitch 72 floats; item norms computed exact-fp32 from the staged tile.
// Epilogue: column-permuted -> pure STG.128 full-sector stores.

#define THREADS   256
#define BN        64
#define BPITCH    288                       // 72 floats per B row
#define BSTAGE_SZ (BN * BPITCH)             // 18432
#define SM_AFRAG  0                         // 8ks x 16mt x 512B = 64KB
#define SM_BSTAGE 65536                     // 2 stages
#define SM_USQ    (SM_BSTAGE + 2 * BSTAGE_SZ)    // 102400 (256 floats)
#define SM_ISQ    (SM_USQ + 1024)                // 103424 (64 floats)
#define SM_TOTAL  (SM_ISQ + 256)                 // 103680 -> 2 CTAs/SM

__device__ __forceinline__ uint32_t smem_u32(const void* p) {
    uint32_t a;
    asm("{ .reg .u64 t; cvta.to.shared.u64 t, %1; cvt.u32.u64 %0, t; }"
        : "=r"(a) : "l"(p));
    return a;
}
__device__ __forceinline__ uint32_t cvt_tf32(float x) {
    uint32_t r;
    asm("cvt.rna.tf32.f32 %0, %1;" : "=r"(r) : "f"(x));
    return r;
}
__device__ __forceinline__ void mma_tf32(float* c, const uint32_t* a,
                                         uint32_t b0, uint32_t b1) {
    asm volatile(
        "mma.sync.aligned.m16n8k8.row.col.f32.tf32.tf32.f32 "
        "{%0,%1,%2,%3}, {%4,%5,%6,%7}, {%8,%9}, {%0,%1,%2,%3};"
        : "+f"(c[0]), "+f"(c[1]), "+f"(c[2]), "+f"(c[3])
        : "r"(a[0]), "r"(a[1]), "r"(a[2]), "r"(a[3]), "r"(b0), "r"(b1));
}
__device__ __forceinline__ void cp_async16(uint32_t dst, const void* src, int sz) {
    asm volatile("cp.async.cg.shared.global [%0], [%1], 16, %2;"
                 :: "r"(dst), "l"(src), "r"(sz) : "memory");
}
__device__ __forceinline__ void cp_commit() {
    asm volatile("cp.async.commit_group;" ::: "memory");
}
__device__ __forceinline__ void cp_wait0() {
    asm volatile("cp.async.wait_group 0;" ::: "memory");
}

// SMEM B row chi <-> item offset within tile (for STG.128 epilogue):
// chi = 16P + 8e + 2j + d  ->  item = 16P + 4j + 2e + d
__device__ __forceinline__ int perm_item(int chi) {
    return (chi & ~15) + (((chi >> 1) & 3) << 2) + (((chi >> 3) & 1) << 1)
         + (chi & 1);
}

// Issue cp.asyncs for one 64-item B tile (4 x 16B chunks per thread).
__device__ __forceinline__ void issueB(const float* __restrict__ I, int tile,
                                       int nItems, uint32_t stageBase, int tid) {
    #pragma unroll
    for (int h = 0; h < 4; h++) {
        const int chunk = tid + h * THREADS;     // 0..1023
        const int chi = chunk >> 4, c = chunk & 15;
        const long item = (long)tile * BN + perm_item(chi);
        const int  valid = item < nItems;
        const float* src = I + (valid ? item * 64 + c * 4 : 0);
        cp_async16(stageBase + chi * BPITCH + c * 16, src, valid ? 16 : 0);
    }
}

__global__ __launch_bounds__(THREADS, 2)
void cml_mma(const int* __restrict__ ids,
             const float* __restrict__ U,
             const float* __restrict__ I,
             float* __restrict__ out,
             int nItems)
{
    extern __shared__ char smem[];
    const uint32_t sb = smem_u32(smem);
    float* usq = (float*)(smem + SM_USQ);
    float* isq = (float*)(smem + SM_ISQ);

    const int tid  = threadIdx.x;
    const int lane = tid & 31;
    const int wid  = tid >> 5;
    const int wm   = wid >> 1;      // 0..3: 64 user rows (4 mtiles)
    const int wn   = wid & 1;       // 0..1: 32 item cols (4 ntiles)

    // ---- Prologue: A (256 users) -> k-permuted tf32 frag layout + usq -----
    {
        const int u = tid;
        const int uid = ids[u];
        const float* up = U + (size_t)uid * 64;
        float a[64];
        #pragma unroll
        for (int w = 0; w < 16; w++) {
            const float4 t = ((const float4*)up)[w];
            a[4*w] = t.x; a[4*w+1] = t.y; a[4*w+2] = t.z; a[4*w+3] = t.w;
        }
        float s = 0.f;
        #pragma unroll
        for (int j = 0; j < 64; j++) s = fmaf(a[j], a[j], s);
        usq[u] = s;

        const int mt = u >> 4, rr = u & 7, r8 = (u >> 3) & 1;
        #pragma unroll
        for (int k = 0; k < 64; k++) {
            const int ks = k >> 3, w = k & 7, m = w >> 1, half = w & 1;
            // raw k-pair (2m, 2m+1) occupies mma k-slots (m, m+4)
            *(uint32_t*)(smem + (ks * 16 + mt) * 512 + (rr * 4 + m) * 16
                         + (r8 + 2 * half) * 4) = cvt_tf32(a[k]);
        }
    }

    // ---- Pipeline prologue: stage 0 ---------------------------------------
    const int NT = (nItems + BN - 1) >> 6;
    issueB(I, blockIdx.x, nItems, sb + SM_BSTAGE, tid);
    cp_commit();

    int it = 0;
    for (int tile = blockIdx.x; tile < NT; tile += gridDim.x, it++) {
        const int stage = it & 1;
        const char* bp = smem + SM_BSTAGE + stage * BSTAGE_SZ;

        cp_wait0();
        __syncthreads();   // stage ready; prev iter fully consumed everywhere

        // ---- item norms (exact fp32) from staged raw B --------------------
        {
            const int chi = tid >> 2, q = tid & 3;
            const char* p = bp + chi * BPITCH + q * 64;
            float s = 0.f;
            #pragma unroll
            for (int w = 0; w < 4; w++) {
                const float4 v = ((const float4*)p)[w];
                s += v.x*v.x + v.y*v.y + v.z*v.z + v.w*v.w;
            }
            s += __shfl_xor_sync(0xffffffffu, s, 1);
            s += __shfl_xor_sync(0xffffffffu, s, 2);
            if (q == 0) isq[chi] = s;          // indexed by SMEM row chi
        }

        // ---- prefetch next tile into the other stage ----------------------
        {
            const int t = tile + gridDim.x;
            if (t < NT)
                issueB(I, t, nItems, sb + SM_BSTAGE + (stage ^ 1) * BSTAGE_SZ,
                       tid);
            cp_commit();
        }
        __syncthreads();   // isq visible to all warps

        // ---- MMA: 4 mtiles x 4 ntiles x 8 ksteps --------------------------
        float acc[4][4][4];
        #pragma unroll
        for (int a = 0; a < 4; a++)
            #pragma unroll
            for (int b = 0; b < 4; b++)
                #pragma unroll
                for (int c = 0; c < 4; c++) acc[a][b][c] = 0.f;

        #pragma unroll
        for (int ks = 0; ks < 8; ks++) {
            uint4 av[4];
            #pragma unroll
            for (int mt = 0; mt < 4; mt++)
                av[mt] = *(const uint4*)(smem + (ks * 16 + wm * 4 + mt) * 512
                                         + lane * 16);
            #pragma unroll
            for (int n = 0; n < 4; n++) {
                // raw fp32 pair (k = ks*8+2m, +1) = mma k-slots (m, m+4)
                const uint2 b = *(const uint2*)(bp
                    + ((wn * 4 + n) * 8 + (lane >> 2)) * BPITCH
                    + ks * 32 + (lane & 3) * 8);
                mma_tf32(acc[0][n], (const uint32_t*)&av[0], b.x, b.y);
                mma_tf32(acc[1][n], (const uint32_t*)&av[1], b.x, b.y);
                mma_tf32(acc[2][n], (const uint32_t*)&av[2], b.x, b.y);
                mma_tf32(acc[3][n], (const uint32_t*)&av[3], b.x, b.y);
            }
        }

        // ---- Epilogue: score = 2c - usq - isq, STG.128 --------------------
        #pragma unroll
        for (int mt = 0; mt < 4; mt++) {
            const int rg = wm * 64 + mt * 16 + (lane >> 2);
            const float u0 = usq[rg], u1 = usq[rg + 8];
            const size_t r0 = (size_t)rg * (size_t)nItems;
            const size_t r1 = r0 + (size_t)8 * (size_t)nItems;
            #pragma unroll
            for (int qh = 0; qh < 2; qh++) {
                const int P = wn * 2 + qh;
                const int col = tile * BN + P * 16 + (lane & 3) * 4;
                if (col < nItems) {
                    const float2 iqa = *(const float2*)&isq[P * 16 + (lane & 3) * 2];
                    const float2 iqb = *(const float2*)&isq[P * 16 + 8 + (lane & 3) * 2];
                    const float* e0 = acc[mt][2 * qh];
                    const float* e1 = acc[mt][2 * qh + 1];
                    float4 v0, v1;
                    v0.x = fmaf(2.f, e0[0], -(u0 + iqa.x));
                    v0.y = fmaf(2.f, e0[1], -(u0 + iqa.y));
                    v0.z = fmaf(2.f, e1[0], -(u0 + iqb.x));
                    v0.w = fmaf(2.f, e1[1], -(u0 + iqb.y));
                    v1.x = fmaf(2.f, e0[2], -(u1 + iqa.x));
                    v1.y = fmaf(2.f, e0[3], -(u1 + iqa.y));
                    v1.z = fmaf(2.f, e1[2], -(u1 + iqb.x));
                    v1.w = fmaf(2.f, e1[3], -(u1 + iqb.y));
                    *(float4*)(out + r0 + col) = v0;
                    *(float4*)(out + r1 + col) = v1;
                }
            }
        }
    }
}

extern "C" void kernel_launch(void* const* d_in, const int* in_sizes, int n_in,
                              void* d_out, int out_size) {
    const int*   ids = (const int*)d_in[0];     // [256]
    const float* U   = (const float*)d_in[1];   // [100000, 64]
    const float* I   = (const float*)d_in[2];   // [500000, 64]
    float*       out = (float*)d_out;           // [256, 500000]

    const int nItems = in_sizes[2] / 64;

    int nsm = 148;
    cudaDeviceGetAttribute(&nsm, cudaDevAttrMultiProcessorCount, 0);

    cudaFuncSetAttribute(cml_mma, cudaFuncAttributeMaxDynamicSharedMemorySize,
                         SM_TOTAL);
    cml_mma<<<2 * nsm, THREADS, SM_TOTAL>>>(ids, U, I, out, nItems);
}

// round 15
// speedup vs baseline: 1.2364x; 1.0508x over previous
#include <cuda_runtime.h>
#include <cstdint>

// CML scores: out[u,i] = 2*dot(U[ids[u]], I[i]) - ||u||^2 - ||i||^2
// GEMM M=256 x N=500000 x K=64, mma.sync.m16n8k8 tf32 (fp32 accum).
// 3 CTAs/SM x 256 threads (independent 8-warp barrier domains).
// Each CTA: 128 users (half = bid&1) x 64-item tiles; half-pairs stream the
// same B tiles concurrently -> second read is ~L2-hit.
// A: converted once (cvt.rna tf32) into frag-layout SMEM (k-permuted).
// B: cp.async.cg raw fp32, 2 stages (HMMA truncates fp32->tf32).
// Epilogue: column-permuted -> pure STG.128 full-sector stores.

#define THREADS   256
#define BM        128
#define BN        64
#define BPITCH    288                       // 72 floats per B row
#define BSTAGE_SZ (BN * BPITCH)             // 18432
#define SM_AFRAG  0                         // 8ks x 8mt x 512B = 32KB
#define SM_BSTAGE 32768                     // 2 stages
#define SM_USQ    (SM_BSTAGE + 2 * BSTAGE_SZ)    // 69632 (128 floats)
#define SM_ISQ    (SM_USQ + 512)                 // 70144 (64 floats)
#define SM_TOTAL  (SM_ISQ + 256)                 // 70400 -> 3 CTAs/SM

__device__ __forceinline__ uint32_t cvt_tf32(float x) {
    uint32_t r;
    asm("cvt.rna.tf32.f32 %0, %1;" : "=r"(r) : "f"(x));
    return r;
}
__device__ __forceinline__ void mma_tf32(float* c, const uint32_t* a,
                                         uint32_t b0, uint32_t b1) {
    asm volatile(
        "mma.sync.aligned.m16n8k8.row.col.f32.tf32.tf32.f32 "
        "{%0,%1,%2,%3}, {%4,%5,%6,%7}, {%8,%9}, {%0,%1,%2,%3};"
        : "+f"(c[0]), "+f"(c[1]), "+f"(c[2]), "+f"(c[3])
        : "r"(a[0]), "r"(a[1]), "r"(a[2]), "r"(a[3]), "r"(b0), "r"(b1));
}
__device__ __forceinline__ uint32_t smem_u32(const void* p) {
    uint32_t a;
    asm("{ .reg .u64 t; cvta.to.shared.u64 t, %1; cvt.u32.u64 %0, t; }"
        : "=r"(a) : "l"(p));
    return a;
}
__device__ __forceinline__ void cp_async16(uint32_t dst, const void* src, int sz) {
    asm volatile("cp.async.cg.shared.global [%0], [%1], 16, %2;"
                 :: "r"(dst), "l"(src), "r"(sz) : "memory");
}
__device__ __forceinline__ void cp_commit() {
    asm volatile("cp.async.commit_group;" ::: "memory");
}
__device__ __forceinline__ void cp_wait0() {
    asm volatile("cp.async.wait_group 0;" ::: "memory");
}

// SMEM B row chi <-> item offset within tile (for STG.128 epilogue):
// chi = 16P + 8e + 2j + d  ->  item = 16P + 4j + 2e + d
__device__ __forceinline__ int perm_item(int chi) {
    return (chi & ~15) + (((chi >> 1) & 3) << 2) + (((chi >> 3) & 1) << 1)
         + (chi & 1);
}

// Issue cp.asyncs for one 64-item B tile (4 x 16B chunks per thread).
__device__ __forceinline__ void issueB(const float* __restrict__ I, int tile,
                                       int nItems, uint32_t stageBase, int tid) {
    #pragma unroll
    for (int h = 0; h < 4; h++) {
        const int chunk = tid + h * THREADS;     // 0..1023
        const int chi = chunk >> 4, c = chunk & 15;
        const long item = (long)tile * BN + perm_item(chi);
        const int  valid = item < nItems;
        const float* src = I + (valid ? item * 64 + c * 4 : 0);
        cp_async16(stageBase + chi * BPITCH + c * 16, src, valid ? 16 : 0);
    }
}

__global__ __launch_bounds__(THREADS, 3)
void cml_mma(const int* __restrict__ ids,
             const float* __restrict__ U,
             const float* __restrict__ I,
             float* __restrict__ out,
             int nItems)
{
    extern __shared__ char smem[];
    const uint32_t sb = smem_u32(smem);
    float* usq = (float*)(smem + SM_USQ);
    float* isq = (float*)(smem + SM_ISQ);

    const int tid  = threadIdx.x;
    const int lane = tid & 31;
    const int wid  = tid >> 5;
    const int wm   = wid >> 1;      // 0..3: 32 user rows (2 mtiles)
    const int wn   = wid & 1;       // 0..1: 32 item cols (4 ntiles)

    const int half    = blockIdx.x & 1;          // which 128 users
    const int stream  = blockIdx.x >> 1;         // item stream
    const int nStream = gridDim.x >> 1;

    // ---- Prologue: A (128 users) -> k-permuted tf32 frag layout + usq -----
    {
        const int u = tid >> 1, hh = tid & 1;    // 32 k-values per thread
        const int uid = ids[half * BM + u];
        const float* up = U + (size_t)uid * 64 + hh * 32;
        float a[32];
        #pragma unroll
        for (int w = 0; w < 8; w++) {
            const float4 t = ((const float4*)up)[w];
            a[4*w] = t.x; a[4*w+1] = t.y; a[4*w+2] = t.z; a[4*w+3] = t.w;
        }
        float s = 0.f;
        #pragma unroll
        for (int j = 0; j < 32; j++) s = fmaf(a[j], a[j], s);
        s += __shfl_xor_sync(0xffffffffu, s, 1);  // pair (hh=0,1), same u
        if (hh == 0) usq[u] = s;

        const int mt = u >> 4, rr = u & 7, r8 = (u >> 3) & 1;
        #pragma unroll
        for (int j = 0; j < 32; j++) {
            const int k = hh * 32 + j;
            const int ks = k >> 3, w = k & 7, m = w >> 1, hlf = w & 1;
            // raw k-pair (2m, 2m+1) occupies mma k-slots (m, m+4)
            *(uint32_t*)(smem + (ks * 8 + mt) * 512 + (rr * 4 + m) * 16
                         + (r8 + 2 * hlf) * 4) = cvt_tf32(a[j]);
        }
    }

    // ---- Pipeline prologue: stage 0 ---------------------------------------
    const int NT = (nItems + BN - 1) >> 6;
    issueB(I, stream, nItems, sb + SM_BSTAGE, tid);
    cp_commit();

    int it = 0;
    for (int tile = stream; tile < NT; tile += nStream, it++) {
        const int stage = it & 1;
        const char* bp = smem + SM_BSTAGE + stage * BSTAGE_SZ;

        cp_wait0();
        __syncthreads();   // stage ready; prev iter fully consumed everywhere

        // ---- item norms (exact fp32) from staged raw B --------------------
        {
            const int chi = tid >> 2, q = tid & 3;
            const char* p = bp + chi * BPITCH + q * 64;
            float s = 0.f;
            #pragma unroll
            for (int w = 0; w < 4; w++) {
                const float4 v = ((const float4*)p)[w];
                s += v.x*v.x + v.y*v.y + v.z*v.z + v.w*v.w;
            }
            s += __shfl_xor_sync(0xffffffffu, s, 1);
            s += __shfl_xor_sync(0xffffffffu, s, 2);
            if (q == 0) isq[chi] = s;          // indexed by SMEM row chi
        }

        // ---- prefetch next tile into the other stage ----------------------
        {
            const int t = tile + nStream;
            if (t < NT)
                issueB(I, t, nItems, sb + SM_BSTAGE + (stage ^ 1) * BSTAGE_SZ,
                       tid);
            cp_commit();
        }
        __syncthreads();   // isq visible to all warps

        // ---- MMA: 2 mtiles x 4 ntiles x 8 ksteps --------------------------
        float acc[2][4][4];
        #pragma unroll
        for (int a = 0; a < 2; a++)
            #pragma unroll
            for (int b = 0; b < 4; b++)
                #pragma unroll
                for (int c = 0; c < 4; c++) acc[a][b][c] = 0.f;

        #pragma unroll
        for (int ks = 0; ks < 8; ks++) {
            uint4 av[2];
            #pragma unroll
            for (int mt = 0; mt < 2; mt++)
                av[mt] = *(const uint4*)(smem + (ks * 8 + wm * 2 + mt) * 512
                                         + lane * 16);
            #pragma unroll
            for (int n = 0; n < 4; n++) {
                // raw fp32 pair (k = ks*8+2m, +1) = mma k-slots (m, m+4)
                const uint2 b = *(const uint2*)(bp
                    + ((wn * 4 + n) * 8 + (lane >> 2)) * BPITCH
                    + ks * 32 + (lane & 3) * 8);
                mma_tf32(acc[0][n], (const uint32_t*)&av[0], b.x, b.y);
                mma_tf32(acc[1][n], (const uint32_t*)&av[1], b.x, b.y);
            }
        }

        // ---- Epilogue: score = 2c - usq - isq, STG.128 --------------------
        #pragma unroll
        for (int mt = 0; mt < 2; mt++) {
            const int rg = wm * 32 + mt * 16 + (lane >> 2);
            const float u0 = usq[rg], u1 = usq[rg + 8];
            const size_t r0 = (size_t)(half * BM + rg) * (size_t)nItems;
            const size_t r1 = r0 + (size_t)8 * (size_t)nItems;
            #pragma unroll
            for (int qh = 0; qh < 2; qh++) {
                const int P = wn * 2 + qh;
                const int col = tile * BN + P * 16 + (lane & 3) * 4;
                if (col < nItems) {
                    const float2 iqa = *(const float2*)&isq[P * 16 + (lane & 3) * 2];
                    const float2 iqb = *(const float2*)&isq[P * 16 + 8 + (lane & 3) * 2];
                    const float* e0 = acc[mt][2 * qh];
                    const float* e1 = acc[mt][2 * qh + 1];
                    float4 v0, v1;
                    v0.x = fmaf(2.f, e0[0], -(u0 + iqa.x));
                    v0.y = fmaf(2.f, e0[1], -(u0 + iqa.y));
                    v0.z = fmaf(2.f, e1[0], -(u0 + iqb.x));
                    v0.w = fmaf(2.f, e1[1], -(u0 + iqb.y));
                    v1.x = fmaf(2.f, e0[2], -(u1 + iqa.x));
                    v1.y = fmaf(2.f, e0[3], -(u1 + iqa.y));
                    v1.z = fmaf(2.f, e1[2], -(u1 + iqb.x));
                    v1.w = fmaf(2.f, e1[3], -(u1 + iqb.y));
                    *(float4*)(out + r0 + col) = v0;
                    *(float4*)(out + r1 + col) = v1;
                }
            }
        }
    }
}

extern "C" void kernel_launch(void* const* d_in, const int* in_sizes, int n_in,
                              void* d_out, int out_size) {
    const int*   ids = (const int*)d_in[0];     // [256]
    const float* U   = (const float*)d_in[1];   // [100000, 64]
    const float* I   = (const float*)d_in[2];   // [500000, 64]
    float*       out = (float*)d_out;           // [256, 500000]

    const int nItems = in_sizes[2] / 64;

    int nsm = 148;
    cudaDeviceGetAttribute(&nsm, cudaDevAttrMultiProcessorCount, 0);

    int grid = 3 * nsm;
    if (grid & 1) grid--;            // need even (user-half pairs)

    cudaFuncSetAttribute(cml_mma, cudaFuncAttributeMaxDynamicSharedMemorySize,
                         SM_TOTAL);
    cml_mma<<<grid, THREADS, SM_TOTAL>>>(ids, U, I, out, nItems);
}